// round 15
// baseline (speedup 1.0000x reference)
#include <cuda_runtime.h>
#include <cuda_fp16.h>
#include <math.h>
#include <cstdint>

// Problem constants
#define TSEQ 2048
#define DMODEL 2048
#define HQ 32
#define HKV 8
#define DHEAD 64
#define DKV (HKV * DHEAD)   // 512

// ---------------------------------------------------------------------------
// Device-global scratch (allocation-free rule). fp16 arrays 16B-aligned.
// ---------------------------------------------------------------------------
__device__ __align__(16) __half g_xh[TSEQ * DMODEL];
__device__ __align__(16) __half g_wh[3072 * DMODEL];
__device__ __align__(16) __half g_woh[DMODEL * DMODEL];
__device__ __align__(16) __half g_qh[TSEQ * DMODEL];
__device__ __align__(16) __half g_kh[TSEQ * DKV];
__device__ __align__(16) __half g_vh[TSEQ * DKV];
__device__ __align__(16) __half g_ah[TSEQ * DMODEL];

// ===========================================================================
// Warp-MMA / async-copy helpers
// ===========================================================================
__device__ __forceinline__ uint32_t smem_u32(const void* p) {
    uint32_t a;
    asm("{ .reg .u64 t; cvta.to.shared.u64 t, %1; cvt.u32.u64 %0, t; }"
        : "=r"(a) : "l"(p));
    return a;
}
__device__ __forceinline__ void ldsm4(uint32_t* r, uint32_t a) {
    asm volatile("ldmatrix.sync.aligned.m8n8.x4.shared.b16 {%0,%1,%2,%3}, [%4];"
                 : "=r"(r[0]), "=r"(r[1]), "=r"(r[2]), "=r"(r[3]) : "r"(a));
}
__device__ __forceinline__ void ldsm4t(uint32_t* r, uint32_t a) {
    asm volatile("ldmatrix.sync.aligned.m8n8.x4.trans.shared.b16 {%0,%1,%2,%3}, [%4];"
                 : "=r"(r[0]), "=r"(r[1]), "=r"(r[2]), "=r"(r[3]) : "r"(a));
}
__device__ __forceinline__ void mma_f16(float* c, const uint32_t* a,
                                        uint32_t b0, uint32_t b1) {
    asm volatile(
        "mma.sync.aligned.m16n8k16.row.col.f32.f16.f16.f32 "
        "{%0,%1,%2,%3}, {%4,%5,%6,%7}, {%8,%9}, {%0,%1,%2,%3};"
        : "+f"(c[0]), "+f"(c[1]), "+f"(c[2]), "+f"(c[3])
        : "r"(a[0]), "r"(a[1]), "r"(a[2]), "r"(a[3]), "r"(b0), "r"(b1));
}
__device__ __forceinline__ void cp_async16(uint32_t dst, const void* src) {
    asm volatile("cp.async.cg.shared.global [%0], [%1], 16;" :: "r"(dst), "l"(src));
}
#define CP_COMMIT() asm volatile("cp.async.commit_group;" ::: "memory")
#define CP_WAIT(N)  asm volatile("cp.async.wait_group %0;" :: "n"(N) : "memory")

__device__ __forceinline__ uint32_t u32of(__half2 h) {
    return *reinterpret_cast<uint32_t*>(&h);
}

// ---------------------------------------------------------------------------
// Fused fp32 -> fp16 conversion for all 5 inputs (one launch, 8 floats/thread)
// ---------------------------------------------------------------------------
#define N4X 1048576
#define N4K 262144
#define N4TOT (3 * N4X + 2 * N4K)
__global__ void cvt_all_kernel(const float* __restrict__ x,
                               const float* __restrict__ Wq,
                               const float* __restrict__ Wk,
                               const float* __restrict__ Wv,
                               const float* __restrict__ Wo) {
    int base = (blockIdx.x * blockDim.x + threadIdx.x) * 2;
#pragma unroll
    for (int u = 0; u < 2; ++u) {
        int i4 = base + u;
        if (i4 >= N4TOT) return;
        const float* src;
        __half* dst;
        int off;
        if (i4 < N4X) {
            src = x; dst = g_xh; off = i4;
        } else if (i4 < 2 * N4X) {
            src = Wq; dst = g_wh; off = i4 - N4X;
        } else if (i4 < 2 * N4X + N4K) {
            src = Wk; dst = g_wh + (size_t)2048 * DMODEL; off = i4 - 2 * N4X;
        } else if (i4 < 2 * N4X + 2 * N4K) {
            src = Wv; dst = g_wh + (size_t)2560 * DMODEL; off = i4 - 2 * N4X - N4K;
        } else {
            src = Wo; dst = g_woh; off = i4 - 2 * N4X - 2 * N4K;
        }
        float4 f = *reinterpret_cast<const float4*>(src + (size_t)off * 4);
        size_t o = (size_t)off * 4;
        *reinterpret_cast<uint32_t*>(dst + o)     = u32of(__floats2half2_rn(f.x, f.y));
        *reinterpret_cast<uint32_t*>(dst + o + 2) = u32of(__floats2half2_rn(f.z, f.w));
    }
}

#define GST 40                         // smem row stride in halves (80B)

// ===========================================================================
// GEMM body A (qkv): CTA 128x128, 8 warps @ 64x32, 3-stage cp.async,
// one __syncthreads per iteration.
// mode 1: fp16 out; mode 2: RoPE + fp16 out.
// ===========================================================================
#define TILE_H (128 * GST)             // 5120 halves
#define STG128_H (2 * TILE_H)
constexpr int QKV_SMEM_BYTES = 3 * STG128_H * 2;   // 61440

__device__ __forceinline__ void qkv_loads(uint32_t sb, int stage,
                                          const __half* A, const __half* B,
                                          int k0, int tid) {
    const __half* bases[2] = {A, B};
    uint32_t dbase = sb + (uint32_t)stage * STG128_H * 2;
#pragma unroll
    for (int it = 0; it < 4; ++it) {
        int slot = tid + it * 256;
        int t = slot >> 9;
        int idx = slot & 511;
        int row = idx >> 2;
        int q = idx & 3;
        cp_async16(dbase + (uint32_t)(t * TILE_H + row * GST + q * 8) * 2,
                   bases[t] + (size_t)row * 2048 + k0 + q * 8);
    }
}

__device__ void qkv_body(const __half* __restrict__ A,
                         const __half* __restrict__ B,
                         int mode, __half* Ch, int ldc,
                         const float* __restrict__ rc,
                         const float* __restrict__ rs,
                         int rbase, int cb) {
    extern __shared__ uint16_t sm16[];
    uint32_t sb = smem_u32(sm16);
    int tid = threadIdx.x;
    int lane = tid & 31;
    int wid = tid >> 5;
    int m0 = (wid & 1) * 64;
    int n0 = (wid >> 1) * 32;

    float acc[4][4][4];
#pragma unroll
    for (int i = 0; i < 4; ++i)
#pragma unroll
        for (int j = 0; j < 4; ++j)
#pragma unroll
            for (int q = 0; q < 4; ++q) acc[i][j][q] = 0.0f;

    qkv_loads(sb, 0, A, B, 0, tid);
    CP_COMMIT();
    qkv_loads(sb, 1, A, B, 32, tid);
    CP_COMMIT();

    int stage = 0;
    for (int i = 0; i < 64; ++i) {
        if (i < 63) { CP_WAIT(1); } else { CP_WAIT(0); }
        __syncthreads();
        if (i + 2 < 64) {
            int ns = stage + 2;
            if (ns >= 3) ns -= 3;
            qkv_loads(sb, ns, A, B, (i + 2) * 32, tid);
            CP_COMMIT();
        }

        uint32_t aA = sb + (uint32_t)stage * STG128_H * 2;
        uint32_t aB = aA + TILE_H * 2;

#pragma unroll
        for (int kk = 0; kk < 2; ++kk) {
            uint32_t ah[4][4];
            int rA = m0 + (lane & 15);
            int cA = kk * 16 + ((lane >> 4) << 3);
#pragma unroll
            for (int i2 = 0; i2 < 4; ++i2)
                ldsm4(ah[i2], aA + (uint32_t)(((rA + 16 * i2) * GST + cA) * 2));
            uint32_t bh[2][4];
            int rB = n0 + (lane & 7) + ((lane >> 3) & 1) * 8;
            int cB = kk * 16 + ((lane >> 4) << 3);
#pragma unroll
            for (int jp = 0; jp < 2; ++jp)
                ldsm4(bh[jp], aB + (uint32_t)(((rB + 16 * jp) * GST + cB) * 2));
#pragma unroll
            for (int i2 = 0; i2 < 4; ++i2)
#pragma unroll
                for (int jp = 0; jp < 2; ++jp) {
                    mma_f16(acc[i2][2 * jp],     ah[i2], bh[jp][0], bh[jp][2]);
                    mma_f16(acc[i2][2 * jp + 1], ah[i2], bh[jp][1], bh[jp][3]);
                }
        }
        if (++stage == 3) stage = 0;
    }

    int r0 = m0 + (lane >> 2);
    int cq = 2 * (lane & 3);
    if (mode == 1) {
#pragma unroll
        for (int i = 0; i < 4; ++i)
#pragma unroll
            for (int j = 0; j < 4; ++j) {
                int row = r0 + 16 * i;
                int col = n0 + 8 * j + cq;
                *reinterpret_cast<uint32_t*>(Ch + (size_t)row * ldc + col) =
                    u32of(__floats2half2_rn(acc[i][j][0], acc[i][j][1]));
                *reinterpret_cast<uint32_t*>(Ch + (size_t)(row + 8) * ldc + col) =
                    u32of(__floats2half2_rn(acc[i][j][2], acc[i][j][3]));
            }
    } else {
        // RoPE fused: acc quads hold adjacent even/odd column pairs
#pragma unroll
        for (int i = 0; i < 4; ++i)
#pragma unroll
            for (int j = 0; j < 4; ++j) {
                int row = r0 + 16 * i;
                int col = n0 + 8 * j + cq;
                int pi = ((cb + col) & 63) >> 1;
                int gr = rbase + row;
                float c0 = rc[gr * 32 + pi], s0 = rs[gr * 32 + pi];
                float o0 = acc[i][j][0] * c0 - acc[i][j][1] * s0;
                float o1 = acc[i][j][0] * s0 + acc[i][j][1] * c0;
                *reinterpret_cast<uint32_t*>(Ch + (size_t)row * ldc + col) =
                    u32of(__floats2half2_rn(o0, o1));
                float c1 = rc[(gr + 8) * 32 + pi], s1 = rs[(gr + 8) * 32 + pi];
                o0 = acc[i][j][2] * c1 - acc[i][j][3] * s1;
                o1 = acc[i][j][2] * s1 + acc[i][j][3] * c1;
                *reinterpret_cast<uint32_t*>(Ch + (size_t)(row + 8) * ldc + col) =
                    u32of(__floats2half2_rn(o0, o1));
            }
    }
}

__global__ __launch_bounds__(256, 2) void qkv_hmma(const float* __restrict__ rc,
                                                   const float* __restrict__ rs) {
    int bm = blockIdx.y * 128;
    int bn = blockIdx.x * 128;
    const __half* A = g_xh + (size_t)bm * DMODEL;
    const __half* B = g_wh + (size_t)bn * DMODEL;
    if (bn < 2048) {
        qkv_body(A, B, 2, g_qh + (size_t)bm * DMODEL + bn, DMODEL, rc, rs, bm, bn);
    } else if (bn < 2560) {
        qkv_body(A, B, 2, g_kh + (size_t)bm * DKV + (bn - 2048), DKV, rc, rs, bm,
                 bn - 2048);
    } else {
        qkv_body(A, B, 1, g_vh + (size_t)bm * DKV + (bn - 2560), DKV,
                 nullptr, nullptr, 0, 0);
    }
}

// ===========================================================================
// GEMM body B (out): CTA 128x256, 8 warps @ 64x64, 3-stage cp.async,
// hoisted fragment loads (both kk) ahead of all MMAs.
// ===========================================================================
#define ATILE_H (128 * GST)            // 5120 halves
#define BTILE_H (256 * GST)            // 10240 halves
#define STG256_H (ATILE_H + BTILE_H)   // 15360 halves
constexpr int OUT_SMEM_BYTES = 3 * STG256_H * 2;   // 92160

__device__ __forceinline__ void out_loads(uint32_t sb, int stage,
                                          const __half* A, const __half* B,
                                          int k0, int tid) {
    uint32_t dbase = sb + (uint32_t)stage * STG256_H * 2;
#pragma unroll
    for (int it = 0; it < 2; ++it) {
        int slot = tid + it * 256;
        int row = slot >> 2;
        int q = slot & 3;
        cp_async16(dbase + (uint32_t)(row * GST + q * 8) * 2,
                   A + (size_t)row * 2048 + k0 + q * 8);
    }
#pragma unroll
    for (int it = 0; it < 4; ++it) {
        int slot = tid + it * 256;
        int row = slot >> 2;
        int q = slot & 3;
        cp_async16(dbase + (uint32_t)(ATILE_H + row * GST + q * 8) * 2,
                   B + (size_t)row * 2048 + k0 + q * 8);
    }
}

__global__ __launch_bounds__(256, 1) void out_hmma(float* __restrict__ out) {
    extern __shared__ uint16_t sm16[];
    uint32_t sb = smem_u32(sm16);
    int bm = blockIdx.y * 128;
    int bn = blockIdx.x * 256;
    const __half* A = g_ah + (size_t)bm * DMODEL;
    const __half* B = g_woh + (size_t)bn * DMODEL;
    float* Cf = out + (size_t)bm * DMODEL + bn;

    int tid = threadIdx.x;
    int lane = tid & 31;
    int wid = tid >> 5;
    int m0 = (wid & 1) * 64;
    int n0 = (wid >> 1) * 64;

    float acc[4][8][4];
#pragma unroll
    for (int i = 0; i < 4; ++i)
#pragma unroll
        for (int j = 0; j < 8; ++j)
#pragma unroll
            for (int q = 0; q < 4; ++q) acc[i][j][q] = 0.0f;

    out_loads(sb, 0, A, B, 0, tid);
    CP_COMMIT();
    out_loads(sb, 1, A, B, 32, tid);
    CP_COMMIT();

    int stage = 0;
    for (int i = 0; i < 64; ++i) {
        if (i < 63) { CP_WAIT(1); } else { CP_WAIT(0); }
        __syncthreads();
        if (i + 2 < 64) {
            int ns = stage + 2;
            if (ns >= 3) ns -= 3;
            out_loads(sb, ns, A, B, (i + 2) * 32, tid);
            CP_COMMIT();
        }

        uint32_t aA = sb + (uint32_t)stage * STG256_H * 2;
        uint32_t aB = aA + ATILE_H * 2;

        uint32_t ah[2][4][4], bh[2][4][4];
        int rA = m0 + (lane & 15);
        int rB = n0 + (lane & 7) + ((lane >> 3) & 1) * 8;
        int cF = ((lane >> 4) << 3);
#pragma unroll
        for (int kk = 0; kk < 2; ++kk) {
#pragma unroll
            for (int i2 = 0; i2 < 4; ++i2)
                ldsm4(ah[kk][i2],
                      aA + (uint32_t)(((rA + 16 * i2) * GST + kk * 16 + cF) * 2));
#pragma unroll
            for (int jp = 0; jp < 4; ++jp)
                ldsm4(bh[kk][jp],
                      aB + (uint32_t)(((rB + 16 * jp) * GST + kk * 16 + cF) * 2));
        }
#pragma unroll
        for (int kk = 0; kk < 2; ++kk)
#pragma unroll
            for (int i2 = 0; i2 < 4; ++i2)
#pragma unroll
                for (int jp = 0; jp < 4; ++jp) {
                    mma_f16(acc[i2][2 * jp],     ah[kk][i2], bh[kk][jp][0], bh[kk][jp][2]);
                    mma_f16(acc[i2][2 * jp + 1], ah[kk][i2], bh[kk][jp][1], bh[kk][jp][3]);
                }
        if (++stage == 3) stage = 0;
    }

    int r0 = m0 + (lane >> 2);
    int cq = 2 * (lane & 3);
#pragma unroll
    for (int i = 0; i < 4; ++i)
#pragma unroll
        for (int j = 0; j < 8; ++j) {
            int row = r0 + 16 * i;
            int col = n0 + 8 * j + cq;
            *reinterpret_cast<float2*>(Cf + (size_t)row * DMODEL + col) =
                make_float2(acc[i][j][0], acc[i][j][1]);
            *reinterpret_cast<float2*>(Cf + (size_t)(row + 8) * DMODEL + col) =
                make_float2(acc[i][j][2], acc[i][j][3]);
        }
}

// ===========================================================================
// FA2-style causal GQA attention, single fp16, BQ=128 / BS=64,
// 3-stage cp.async K/V (prefetch depth 2), base-2 online softmax,
// triangle-balanced, fully-masked-tile skip for warps 0-3.
// 256 threads (8 warps), 16 q-rows/warp.
// ===========================================================================
#define AST 72   // smem row stride in halves (144B)
#define KVSTG_H (2 * 64 * AST)          // K+V per stage (9216 halves)
constexpr int ATTN_SMEM_BYTES = (128 * AST + 3 * KVSTG_H) * 2;   // 73728

__global__ __launch_bounds__(256, 2) void attn_hmma() {
    extern __shared__ uint16_t sm16[];
    uint16_t* sQ = sm16;
    uint32_t aQ = smem_u32(sQ);
    uint32_t aKV = aQ + 128 * AST * 2;   // 3 stages follow

    int tid = threadIdx.x;
    int lane = tid & 31;
    int w = tid >> 5;
    int h = blockIdx.y;
    int kvh = h >> 2;
    const float SCALE2 = 0.125f * 1.44269504088896f;   // 1/sqrt(64) * log2(e)

    for (int pass = 0; pass < 2; ++pass) {
        int qt = pass == 0 ? (int)blockIdx.x : 15 - (int)blockIdx.x;

        __syncthreads();
#pragma unroll
        for (int it = 0; it < 4; ++it) {
            int slot = tid + it * 256;
            int r = slot >> 3;
            int q = slot & 7;
            const __half* src =
                g_qh + (size_t)(qt * 128 + r) * DMODEL + h * DHEAD + q * 8;
            *reinterpret_cast<uint4*>(sQ + r * AST + q * 8) =
                *reinterpret_cast<const uint4*>(src);
        }
        __syncthreads();

        uint32_t qf[4][4];
        {
            int rQ = 16 * w + (lane & 15);
            int cF = ((lane >> 4) << 3);
#pragma unroll
            for (int kk = 0; kk < 4; ++kk)
                ldsm4(qf[kk], aQ + (uint32_t)((rQ * AST + cF + 16 * kk) * 2));
        }

        float m0 = -1e30f, m1 = -1e30f, l0 = 0.0f, l1 = 0.0f;
        float oac[8][4];
#pragma unroll
        for (int j = 0; j < 8; ++j)
#pragma unroll
            for (int q = 0; q < 4; ++q) oac[j][q] = 0.0f;

        int nst = 2 * qt + 2;

        auto load_kv = [&](int st, int stg) {
            uint32_t dbase = aKV + (uint32_t)stg * KVSTG_H * 2;
#pragma unroll
            for (int it = 0; it < 4; ++it) {
                int slot = tid + it * 256;
                int t = slot >> 9;
                int r = (slot >> 3) & 63;
                int q = slot & 7;
                const __half* src = (t ? g_vh : g_kh) +
                    (size_t)(st * 64 + r) * DKV + kvh * DHEAD + q * 8;
                uint32_t dst = dbase + (uint32_t)(t * 64 * AST + r * AST + q * 8) * 2;
                cp_async16(dst, src);
            }
        };

        load_kv(0, 0);
        CP_COMMIT();
        if (nst > 1) {
            load_kv(1, 1);
            CP_COMMIT();
        }

        int stg = 0;
        for (int st = 0; st < nst; ++st) {
            if (st + 1 < nst) { CP_WAIT(1); } else { CP_WAIT(0); }
            __syncthreads();
            if (st + 2 < nst) {
                int ns = stg + 2;
                if (ns >= 3) ns -= 3;
                load_kv(st + 2, ns);
                CP_COMMIT();
            }
            uint32_t aK = aKV + (uint32_t)stg * KVSTG_H * 2;
            uint32_t aV = aK + 64 * AST * 2;

            // Warps 0-3 (q rows 0..63) are fully masked on the last diagonal
            // tile (keys 64..127 of the same 128-row block): skip their MMAs.
            bool skip = (st == 2 * qt + 1) && (w < 4);

            float sa[8][4];
#pragma unroll
            for (int j = 0; j < 8; ++j)
#pragma unroll
                for (int q = 0; q < 4; ++q) sa[j][q] = 0.0f;

            int rB = (lane & 7) + ((lane >> 3) & 1) * 8;
            int cF = ((lane >> 4) << 3);
            if (!skip) {
#pragma unroll
                for (int kk = 0; kk < 4; ++kk) {
                    uint32_t kb[4][4];
#pragma unroll
                    for (int jp = 0; jp < 4; ++jp)
                        ldsm4(kb[jp], aK + (uint32_t)(((rB + 16 * jp) * AST + cF + 16 * kk) * 2));
#pragma unroll
                    for (int jp = 0; jp < 4; ++jp) {
                        mma_f16(sa[2 * jp],     qf[kk], kb[jp][0], kb[jp][2]);
                        mma_f16(sa[2 * jp + 1], qf[kk], kb[jp][1], kb[jp][3]);
                    }
                }
            }

            if (st >= 2 * qt) {
                int dd = 16 * w + (lane >> 2) - (st - 2 * qt) * 64;
#pragma unroll
                for (int j = 0; j < 8; ++j) {
                    int c = 8 * j + 2 * (lane & 3);
                    if (c > dd)         sa[j][0] = -1e30f;
                    if (c + 1 > dd)     sa[j][1] = -1e30f;
                    if (c > dd + 8)     sa[j][2] = -1e30f;
                    if (c + 1 > dd + 8) sa[j][3] = -1e30f;
                }
            }

            // ---- base-2 online softmax ----
            float rmax0 = -1e30f, rmax1 = -1e30f;
#pragma unroll
            for (int j = 0; j < 8; ++j) {
                rmax0 = fmaxf(rmax0, fmaxf(sa[j][0], sa[j][1]));
                rmax1 = fmaxf(rmax1, fmaxf(sa[j][2], sa[j][3]));
            }
#pragma unroll
            for (int off = 1; off < 4; off <<= 1) {
                rmax0 = fmaxf(rmax0, __shfl_xor_sync(0xffffffffu, rmax0, off));
                rmax1 = fmaxf(rmax1, __shfl_xor_sync(0xffffffffu, rmax1, off));
            }
            float mn0 = fmaxf(m0, SCALE2 * rmax0);
            float mn1 = fmaxf(m1, SCALE2 * rmax1);
            float al0 = exp2f(m0 - mn0);
            float al1 = exp2f(m1 - mn1);

            uint32_t pa[4][4];
            float rs0 = 0.0f, rs1 = 0.0f;
#pragma unroll
            for (int j = 0; j < 8; ++j) {
                float p0 = exp2f(fmaf(SCALE2, sa[j][0], -mn0));
                float p1 = exp2f(fmaf(SCALE2, sa[j][1], -mn0));
                float p2 = exp2f(fmaf(SCALE2, sa[j][2], -mn1));
                float p3 = exp2f(fmaf(SCALE2, sa[j][3], -mn1));
                rs0 += p0 + p1;
                rs1 += p2 + p3;
                pa[j >> 1][(j & 1) ? 2 : 0] = u32of(__floats2half2_rn(p0, p1));
                pa[j >> 1][(j & 1) ? 3 : 1] = u32of(__floats2half2_rn(p2, p3));
            }
#pragma unroll
            for (int off = 1; off < 4; off <<= 1) {
                rs0 += __shfl_xor_sync(0xffffffffu, rs0, off);
                rs1 += __shfl_xor_sync(0xffffffffu, rs1, off);
            }
            l0 = l0 * al0 + rs0;
            l1 = l1 * al1 + rs1;
            m0 = mn0;
            m1 = mn1;
#pragma unroll
            for (int j = 0; j < 8; ++j) {
                oac[j][0] *= al0;
                oac[j][1] *= al0;
                oac[j][2] *= al1;
                oac[j][3] *= al1;
            }

            if (!skip) {
#pragma unroll
                for (int ks = 0; ks < 4; ++ks) {
                    uint32_t vh[4][4];
                    int row = 16 * ks + (lane & 7) + ((lane >> 3) & 1) * 8;
#pragma unroll
                    for (int jp = 0; jp < 4; ++jp) {
                        int col = 16 * jp + ((lane >> 4) << 3);
                        ldsm4t(vh[jp], aV + (uint32_t)((row * AST + col) * 2));
                    }
#pragma unroll
                    for (int jp = 0; jp < 4; ++jp) {
                        mma_f16(oac[2 * jp],     pa[ks], vh[jp][0], vh[jp][1]);
                        mma_f16(oac[2 * jp + 1], pa[ks], vh[jp][2], vh[jp][3]);
                    }
                }
            }
            if (++stg == 3) stg = 0;
        }

        float inv0 = 1.0f / l0;
        float inv1 = 1.0f / l1;
        int row = qt * 128 + 16 * w + (lane >> 2);
        size_t ob = (size_t)row * DMODEL + h * DHEAD;
#pragma unroll
        for (int j = 0; j < 8; ++j) {
            int col = 8 * j + 2 * (lane & 3);
            *reinterpret_cast<uint32_t*>(g_ah + ob + col) =
                u32of(__floats2half2_rn(oac[j][0] * inv0, oac[j][1] * inv0));
            *reinterpret_cast<uint32_t*>(g_ah + ob + (size_t)8 * DMODEL + col) =
                u32of(__floats2half2_rn(oac[j][2] * inv1, oac[j][3] * inv1));
        }
    }
}

// ---------------------------------------------------------------------------
extern "C" void kernel_launch(void* const* d_in, const int* in_sizes, int n_in,
                              void* d_out, int out_size) {
    const float* x  = (const float*)d_in[0];
    const float* Wq = (const float*)d_in[1];
    const float* Wk = (const float*)d_in[2];
    const float* Wv = (const float*)d_in[3];
    const float* Wo = (const float*)d_in[4];
    const float* rc = (const float*)d_in[5];
    const float* rs = (const float*)d_in[6];
    float* out = (float*)d_out;

    static bool attrs_set = false;
    if (!attrs_set) {
        cudaFuncSetAttribute(attn_hmma, cudaFuncAttributeMaxDynamicSharedMemorySize,
                             ATTN_SMEM_BYTES);
        cudaFuncSetAttribute(qkv_hmma, cudaFuncAttributeMaxDynamicSharedMemorySize,
                             QKV_SMEM_BYTES);
        cudaFuncSetAttribute(out_hmma, cudaFuncAttributeMaxDynamicSharedMemorySize,
                             OUT_SMEM_BYTES);
        attrs_set = true;
    }

    // 0) One fused conversion kernel (x, Wq, Wk, Wv, Wo -> fp16)
    cvt_all_kernel<<<(N4TOT / 2 + 255) / 256, 256>>>(x, Wq, Wk, Wv, Wo);

    // 1) Fused QKV projection + RoPE epilogue (128x128, 3-stage)
    qkv_hmma<<<dim3(24, 16), 256, QKV_SMEM_BYTES>>>(rc, rs);

    // 2) Causal GQA attention (BQ=128, 3-stage KV prefetch, base-2 softmax,
    //    masked-diagonal skip)
    attn_hmma<<<dim3(8, HQ), 256, ATTN_SMEM_BYTES>>>();

    // 3) Output projection (128x256, 3-stage, hoisted fragments)
    out_hmma<<<dim3(8, 16), 256, OUT_SMEM_BYTES>>>(out);
}

// round 16
// speedup vs baseline: 1.0008x; 1.0008x over previous
#include <cuda_runtime.h>
#include <cuda_fp16.h>
#include <math.h>
#include <cstdint>

// Problem constants
#define TSEQ 2048
#define DMODEL 2048
#define HQ 32
#define HKV 8
#define DHEAD 64
#define DKV (HKV * DHEAD)   // 512

// ---------------------------------------------------------------------------
// Device-global scratch (allocation-free rule). fp16 arrays 16B-aligned.
// ---------------------------------------------------------------------------
__device__ __align__(16) __half g_xh[TSEQ * DMODEL];
__device__ __align__(16) __half g_wh[3072 * DMODEL];
__device__ __align__(16) __half g_woh[DMODEL * DMODEL];
__device__ __align__(16) __half g_qh[TSEQ * DMODEL];
__device__ __align__(16) __half g_kh[TSEQ * DKV];
__device__ __align__(16) __half g_vh[TSEQ * DKV];
__device__ __align__(16) __half g_ah[TSEQ * DMODEL];

// ===========================================================================
// Warp-MMA / async-copy helpers
// ===========================================================================
__device__ __forceinline__ uint32_t smem_u32(const void* p) {
    uint32_t a;
    asm("{ .reg .u64 t; cvta.to.shared.u64 t, %1; cvt.u32.u64 %0, t; }"
        : "=r"(a) : "l"(p));
    return a;
}
__device__ __forceinline__ void ldsm4(uint32_t* r, uint32_t a) {
    asm volatile("ldmatrix.sync.aligned.m8n8.x4.shared.b16 {%0,%1,%2,%3}, [%4];"
                 : "=r"(r[0]), "=r"(r[1]), "=r"(r[2]), "=r"(r[3]) : "r"(a));
}
__device__ __forceinline__ void ldsm4t(uint32_t* r, uint32_t a) {
    asm volatile("ldmatrix.sync.aligned.m8n8.x4.trans.shared.b16 {%0,%1,%2,%3}, [%4];"
                 : "=r"(r[0]), "=r"(r[1]), "=r"(r[2]), "=r"(r[3]) : "r"(a));
}
__device__ __forceinline__ void mma_f16(float* c, const uint32_t* a,
                                        uint32_t b0, uint32_t b1) {
    asm volatile(
        "mma.sync.aligned.m16n8k16.row.col.f32.f16.f16.f32 "
        "{%0,%1,%2,%3}, {%4,%5,%6,%7}, {%8,%9}, {%0,%1,%2,%3};"
        : "+f"(c[0]), "+f"(c[1]), "+f"(c[2]), "+f"(c[3])
        : "r"(a[0]), "r"(a[1]), "r"(a[2]), "r"(a[3]), "r"(b0), "r"(b1));
}
__device__ __forceinline__ void cp_async16(uint32_t dst, const void* src) {
    asm volatile("cp.async.cg.shared.global [%0], [%1], 16;" :: "r"(dst), "l"(src));
}
#define CP_COMMIT() asm volatile("cp.async.commit_group;" ::: "memory")
#define CP_WAIT(N)  asm volatile("cp.async.wait_group %0;" :: "n"(N) : "memory")

__device__ __forceinline__ uint32_t u32of(__half2 h) {
    return *reinterpret_cast<uint32_t*>(&h);
}

// ---------------------------------------------------------------------------
// Fused fp32 -> fp16 conversion for all 5 inputs (one launch)
// ---------------------------------------------------------------------------
#define N4X 1048576
#define N4K 262144
__global__ void cvt_all_kernel(const float* __restrict__ x,
                               const float* __restrict__ Wq,
                               const float* __restrict__ Wk,
                               const float* __restrict__ Wv,
                               const float* __restrict__ Wo) {
    int i4 = blockIdx.x * blockDim.x + threadIdx.x;
    const float* src;
    __half* dst;
    int off;
    if (i4 < N4X) {
        src = x; dst = g_xh; off = i4;
    } else if (i4 < 2 * N4X) {
        src = Wq; dst = g_wh; off = i4 - N4X;
    } else if (i4 < 2 * N4X + N4K) {
        src = Wk; dst = g_wh + (size_t)2048 * DMODEL; off = i4 - 2 * N4X;
    } else if (i4 < 2 * N4X + 2 * N4K) {
        src = Wv; dst = g_wh + (size_t)2560 * DMODEL; off = i4 - 2 * N4X - N4K;
    } else {
        src = Wo; dst = g_woh; off = i4 - 2 * N4X - 2 * N4K;
    }
    float4 f = *reinterpret_cast<const float4*>(src + (size_t)off * 4);
    size_t o = (size_t)off * 4;
    *reinterpret_cast<uint32_t*>(dst + o)     = u32of(__floats2half2_rn(f.x, f.y));
    *reinterpret_cast<uint32_t*>(dst + o + 2) = u32of(__floats2half2_rn(f.z, f.w));
}

#define GST 40                         // smem row stride in halves (80B)

// ===========================================================================
// GEMM body A (qkv): CTA 128x128, 8 warps @ 64x32, 3-stage cp.async,
// one __syncthreads per iteration.
// mode 1: fp16 out; mode 2: RoPE + fp16 out.
// ===========================================================================
#define TILE_H (128 * GST)             // 5120 halves
#define STG128_H (2 * TILE_H)
constexpr int QKV_SMEM_BYTES = 3 * STG128_H * 2;   // 61440

__device__ __forceinline__ void qkv_loads(uint32_t sb, int stage,
                                          const __half* A, const __half* B,
                                          int k0, int tid) {
    const __half* bases[2] = {A, B};
    uint32_t dbase = sb + (uint32_t)stage * STG128_H * 2;
#pragma unroll
    for (int it = 0; it < 4; ++it) {
        int slot = tid + it * 256;
        int t = slot >> 9;
        int idx = slot & 511;
        int row = idx >> 2;
        int q = idx & 3;
        cp_async16(dbase + (uint32_t)(t * TILE_H + row * GST + q * 8) * 2,
                   bases[t] + (size_t)row * 2048 + k0 + q * 8);
    }
}

__device__ void qkv_body(const __half* __restrict__ A,
                         const __half* __restrict__ B,
                         int mode, __half* Ch, int ldc,
                         const float* __restrict__ rc,
                         const float* __restrict__ rs,
                         int rbase, int cb) {
    extern __shared__ uint16_t sm16[];
    uint32_t sb = smem_u32(sm16);
    int tid = threadIdx.x;
    int lane = tid & 31;
    int wid = tid >> 5;
    int m0 = (wid & 1) * 64;
    int n0 = (wid >> 1) * 32;

    float acc[4][4][4];
#pragma unroll
    for (int i = 0; i < 4; ++i)
#pragma unroll
        for (int j = 0; j < 4; ++j)
#pragma unroll
            for (int q = 0; q < 4; ++q) acc[i][j][q] = 0.0f;

    qkv_loads(sb, 0, A, B, 0, tid);
    CP_COMMIT();
    qkv_loads(sb, 1, A, B, 32, tid);
    CP_COMMIT();

    int stage = 0;
    for (int i = 0; i < 64; ++i) {
        if (i < 63) { CP_WAIT(1); } else { CP_WAIT(0); }
        __syncthreads();
        if (i + 2 < 64) {
            int ns = stage + 2;
            if (ns >= 3) ns -= 3;
            qkv_loads(sb, ns, A, B, (i + 2) * 32, tid);
            CP_COMMIT();
        }

        uint32_t aA = sb + (uint32_t)stage * STG128_H * 2;
        uint32_t aB = aA + TILE_H * 2;

#pragma unroll
        for (int kk = 0; kk < 2; ++kk) {
            uint32_t ah[4][4];
            int rA = m0 + (lane & 15);
            int cA = kk * 16 + ((lane >> 4) << 3);
#pragma unroll
            for (int i2 = 0; i2 < 4; ++i2)
                ldsm4(ah[i2], aA + (uint32_t)(((rA + 16 * i2) * GST + cA) * 2));
            uint32_t bh[2][4];
            int rB = n0 + (lane & 7) + ((lane >> 3) & 1) * 8;
            int cB = kk * 16 + ((lane >> 4) << 3);
#pragma unroll
            for (int jp = 0; jp < 2; ++jp)
                ldsm4(bh[jp], aB + (uint32_t)(((rB + 16 * jp) * GST + cB) * 2));
#pragma unroll
            for (int i2 = 0; i2 < 4; ++i2)
#pragma unroll
                for (int jp = 0; jp < 2; ++jp) {
                    mma_f16(acc[i2][2 * jp],     ah[i2], bh[jp][0], bh[jp][2]);
                    mma_f16(acc[i2][2 * jp + 1], ah[i2], bh[jp][1], bh[jp][3]);
                }
        }
        if (++stage == 3) stage = 0;
    }

    int r0 = m0 + (lane >> 2);
    int cq = 2 * (lane & 3);
    if (mode == 1) {
#pragma unroll
        for (int i = 0; i < 4; ++i)
#pragma unroll
            for (int j = 0; j < 4; ++j) {
                int row = r0 + 16 * i;
                int col = n0 + 8 * j + cq;
                *reinterpret_cast<uint32_t*>(Ch + (size_t)row * ldc + col) =
                    u32of(__floats2half2_rn(acc[i][j][0], acc[i][j][1]));
                *reinterpret_cast<uint32_t*>(Ch + (size_t)(row + 8) * ldc + col) =
                    u32of(__floats2half2_rn(acc[i][j][2], acc[i][j][3]));
            }
    } else {
        // RoPE fused: acc quads hold adjacent even/odd column pairs
#pragma unroll
        for (int i = 0; i < 4; ++i)
#pragma unroll
            for (int j = 0; j < 4; ++j) {
                int row = r0 + 16 * i;
                int col = n0 + 8 * j + cq;
                int pi = ((cb + col) & 63) >> 1;
                int gr = rbase + row;
                float c0 = rc[gr * 32 + pi], s0 = rs[gr * 32 + pi];
                float o0 = acc[i][j][0] * c0 - acc[i][j][1] * s0;
                float o1 = acc[i][j][0] * s0 + acc[i][j][1] * c0;
                *reinterpret_cast<uint32_t*>(Ch + (size_t)row * ldc + col) =
                    u32of(__floats2half2_rn(o0, o1));
                float c1 = rc[(gr + 8) * 32 + pi], s1 = rs[(gr + 8) * 32 + pi];
                o0 = acc[i][j][2] * c1 - acc[i][j][3] * s1;
                o1 = acc[i][j][2] * s1 + acc[i][j][3] * c1;
                *reinterpret_cast<uint32_t*>(Ch + (size_t)(row + 8) * ldc + col) =
                    u32of(__floats2half2_rn(o0, o1));
            }
    }
}

__global__ __launch_bounds__(256, 2) void qkv_hmma(const float* __restrict__ rc,
                                                   const float* __restrict__ rs) {
    int bm = blockIdx.y * 128;
    int bn = blockIdx.x * 128;
    const __half* A = g_xh + (size_t)bm * DMODEL;
    const __half* B = g_wh + (size_t)bn * DMODEL;
    if (bn < 2048) {
        qkv_body(A, B, 2, g_qh + (size_t)bm * DMODEL + bn, DMODEL, rc, rs, bm, bn);
    } else if (bn < 2560) {
        qkv_body(A, B, 2, g_kh + (size_t)bm * DKV + (bn - 2048), DKV, rc, rs, bm,
                 bn - 2048);
    } else {
        qkv_body(A, B, 1, g_vh + (size_t)bm * DKV + (bn - 2560), DKV,
                 nullptr, nullptr, 0, 0);
    }
}

// ===========================================================================
// GEMM body B (out): CTA 128x256, 8 warps @ 64x64, 3-stage cp.async,
// hoisted fragment loads (both kk) ahead of all MMAs.
// ===========================================================================
#define ATILE_H (128 * GST)            // 5120 halves
#define BTILE_H (256 * GST)            // 10240 halves
#define STG256_H (ATILE_H + BTILE_H)   // 15360 halves
constexpr int OUT_SMEM_BYTES = 3 * STG256_H * 2;   // 92160

__device__ __forceinline__ void out_loads(uint32_t sb, int stage,
                                          const __half* A, const __half* B,
                                          int k0, int tid) {
    uint32_t dbase = sb + (uint32_t)stage * STG256_H * 2;
#pragma unroll
    for (int it = 0; it < 2; ++it) {
        int slot = tid + it * 256;
        int row = slot >> 2;
        int q = slot & 3;
        cp_async16(dbase + (uint32_t)(row * GST + q * 8) * 2,
                   A + (size_t)row * 2048 + k0 + q * 8);
    }
#pragma unroll
    for (int it = 0; it < 4; ++it) {
        int slot = tid + it * 256;
        int row = slot >> 2;
        int q = slot & 3;
        cp_async16(dbase + (uint32_t)(ATILE_H + row * GST + q * 8) * 2,
                   B + (size_t)row * 2048 + k0 + q * 8);
    }
}

__global__ __launch_bounds__(256, 1) void out_hmma(float* __restrict__ out) {
    extern __shared__ uint16_t sm16[];
    uint32_t sb = smem_u32(sm16);
    int bm = blockIdx.y * 128;
    int bn = blockIdx.x * 256;
    const __half* A = g_ah + (size_t)bm * DMODEL;
    const __half* B = g_woh + (size_t)bn * DMODEL;
    float* Cf = out + (size_t)bm * DMODEL + bn;

    int tid = threadIdx.x;
    int lane = tid & 31;
    int wid = tid >> 5;
    int m0 = (wid & 1) * 64;
    int n0 = (wid >> 1) * 64;

    float acc[4][8][4];
#pragma unroll
    for (int i = 0; i < 4; ++i)
#pragma unroll
        for (int j = 0; j < 8; ++j)
#pragma unroll
            for (int q = 0; q < 4; ++q) acc[i][j][q] = 0.0f;

    out_loads(sb, 0, A, B, 0, tid);
    CP_COMMIT();
    out_loads(sb, 1, A, B, 32, tid);
    CP_COMMIT();

    int stage = 0;
    for (int i = 0; i < 64; ++i) {
        if (i < 63) { CP_WAIT(1); } else { CP_WAIT(0); }
        __syncthreads();
        if (i + 2 < 64) {
            int ns = stage + 2;
            if (ns >= 3) ns -= 3;
            out_loads(sb, ns, A, B, (i + 2) * 32, tid);
            CP_COMMIT();
        }

        uint32_t aA = sb + (uint32_t)stage * STG256_H * 2;
        uint32_t aB = aA + ATILE_H * 2;

        uint32_t ah[2][4][4], bh[2][4][4];
        int rA = m0 + (lane & 15);
        int rB = n0 + (lane & 7) + ((lane >> 3) & 1) * 8;
        int cF = ((lane >> 4) << 3);
#pragma unroll
        for (int kk = 0; kk < 2; ++kk) {
#pragma unroll
            for (int i2 = 0; i2 < 4; ++i2)
                ldsm4(ah[kk][i2],
                      aA + (uint32_t)(((rA + 16 * i2) * GST + kk * 16 + cF) * 2));
#pragma unroll
            for (int jp = 0; jp < 4; ++jp)
                ldsm4(bh[kk][jp],
                      aB + (uint32_t)(((rB + 16 * jp) * GST + kk * 16 + cF) * 2));
        }
#pragma unroll
        for (int kk = 0; kk < 2; ++kk)
#pragma unroll
            for (int i2 = 0; i2 < 4; ++i2)
#pragma unroll
                for (int jp = 0; jp < 4; ++jp) {
                    mma_f16(acc[i2][2 * jp],     ah[kk][i2], bh[kk][jp][0], bh[kk][jp][2]);
                    mma_f16(acc[i2][2 * jp + 1], ah[kk][i2], bh[kk][jp][1], bh[kk][jp][3]);
                }
        if (++stage == 3) stage = 0;
    }

    int r0 = m0 + (lane >> 2);
    int cq = 2 * (lane & 3);
#pragma unroll
    for (int i = 0; i < 4; ++i)
#pragma unroll
        for (int j = 0; j < 8; ++j) {
            int row = r0 + 16 * i;
            int col = n0 + 8 * j + cq;
            *reinterpret_cast<float2*>(Cf + (size_t)row * DMODEL + col) =
                make_float2(acc[i][j][0], acc[i][j][1]);
            *reinterpret_cast<float2*>(Cf + (size_t)(row + 8) * DMODEL + col) =
                make_float2(acc[i][j][2], acc[i][j][3]);
        }
}

// ===========================================================================
// FA2-style causal GQA attention, single fp16, BQ=128 / BS=64,
// 3-stage cp.async K/V (prefetch depth 2), base-2 online softmax,
// triangle-balanced. 256 threads (8 warps), 16 q-rows/warp.
// ===========================================================================
#define AST 72   // smem row stride in halves (144B)
#define KVSTG_H (2 * 64 * AST)          // K+V per stage (9216 halves)
constexpr int ATTN_SMEM_BYTES = (128 * AST + 3 * KVSTG_H) * 2;   // 73728

__global__ __launch_bounds__(256, 2) void attn_hmma() {
    extern __shared__ uint16_t sm16[];
    uint16_t* sQ = sm16;
    uint32_t aQ = smem_u32(sQ);
    uint32_t aKV = aQ + 128 * AST * 2;   // 3 stages follow

    int tid = threadIdx.x;
    int lane = tid & 31;
    int w = tid >> 5;
    int h = blockIdx.y;
    int kvh = h >> 2;
    const float SCALE2 = 0.125f * 1.44269504088896f;   // 1/sqrt(64) * log2(e)

    for (int pass = 0; pass < 2; ++pass) {
        int qt = pass == 0 ? (int)blockIdx.x : 15 - (int)blockIdx.x;

        __syncthreads();
#pragma unroll
        for (int it = 0; it < 4; ++it) {
            int slot = tid + it * 256;
            int r = slot >> 3;
            int q = slot & 7;
            const __half* src =
                g_qh + (size_t)(qt * 128 + r) * DMODEL + h * DHEAD + q * 8;
            *reinterpret_cast<uint4*>(sQ + r * AST + q * 8) =
                *reinterpret_cast<const uint4*>(src);
        }
        __syncthreads();

        uint32_t qf[4][4];
        {
            int rQ = 16 * w + (lane & 15);
            int cF = ((lane >> 4) << 3);
#pragma unroll
            for (int kk = 0; kk < 4; ++kk)
                ldsm4(qf[kk], aQ + (uint32_t)((rQ * AST + cF + 16 * kk) * 2));
        }

        float m0 = -1e30f, m1 = -1e30f, l0 = 0.0f, l1 = 0.0f;
        float oac[8][4];
#pragma unroll
        for (int j = 0; j < 8; ++j)
#pragma unroll
            for (int q = 0; q < 4; ++q) oac[j][q] = 0.0f;

        int nst = 2 * qt + 2;

        auto load_kv = [&](int st, int stg) {
            uint32_t dbase = aKV + (uint32_t)stg * KVSTG_H * 2;
#pragma unroll
            for (int it = 0; it < 4; ++it) {
                int slot = tid + it * 256;
                int t = slot >> 9;
                int r = (slot >> 3) & 63;
                int q = slot & 7;
                const __half* src = (t ? g_vh : g_kh) +
                    (size_t)(st * 64 + r) * DKV + kvh * DHEAD + q * 8;
                uint32_t dst = dbase + (uint32_t)(t * 64 * AST + r * AST + q * 8) * 2;
                cp_async16(dst, src);
            }
        };

        load_kv(0, 0);
        CP_COMMIT();
        if (nst > 1) {
            load_kv(1, 1);
            CP_COMMIT();
        }

        int stg = 0;
        for (int st = 0; st < nst; ++st) {
            if (st + 1 < nst) { CP_WAIT(1); } else { CP_WAIT(0); }
            __syncthreads();
            if (st + 2 < nst) {
                int ns = stg + 2;
                if (ns >= 3) ns -= 3;
                load_kv(st + 2, ns);
                CP_COMMIT();
            }
            uint32_t aK = aKV + (uint32_t)stg * KVSTG_H * 2;
            uint32_t aV = aK + 64 * AST * 2;

            float sa[8][4];
#pragma unroll
            for (int j = 0; j < 8; ++j)
#pragma unroll
                for (int q = 0; q < 4; ++q) sa[j][q] = 0.0f;

            int rB = (lane & 7) + ((lane >> 3) & 1) * 8;
            int cF = ((lane >> 4) << 3);
#pragma unroll
            for (int kk = 0; kk < 4; ++kk) {
                uint32_t kb[4][4];
#pragma unroll
                for (int jp = 0; jp < 4; ++jp)
                    ldsm4(kb[jp], aK + (uint32_t)(((rB + 16 * jp) * AST + cF + 16 * kk) * 2));
#pragma unroll
                for (int jp = 0; jp < 4; ++jp) {
                    mma_f16(sa[2 * jp],     qf[kk], kb[jp][0], kb[jp][2]);
                    mma_f16(sa[2 * jp + 1], qf[kk], kb[jp][1], kb[jp][3]);
                }
            }

            if (st >= 2 * qt) {
                int dd = 16 * w + (lane >> 2) - (st - 2 * qt) * 64;
#pragma unroll
                for (int j = 0; j < 8; ++j) {
                    int c = 8 * j + 2 * (lane & 3);
                    if (c > dd)         sa[j][0] = -1e30f;
                    if (c + 1 > dd)     sa[j][1] = -1e30f;
                    if (c > dd + 8)     sa[j][2] = -1e30f;
                    if (c + 1 > dd + 8) sa[j][3] = -1e30f;
                }
            }

            // ---- base-2 online softmax ----
            float rmax0 = -1e30f, rmax1 = -1e30f;
#pragma unroll
            for (int j = 0; j < 8; ++j) {
                rmax0 = fmaxf(rmax0, fmaxf(sa[j][0], sa[j][1]));
                rmax1 = fmaxf(rmax1, fmaxf(sa[j][2], sa[j][3]));
            }
#pragma unroll
            for (int off = 1; off < 4; off <<= 1) {
                rmax0 = fmaxf(rmax0, __shfl_xor_sync(0xffffffffu, rmax0, off));
                rmax1 = fmaxf(rmax1, __shfl_xor_sync(0xffffffffu, rmax1, off));
            }
            float mn0 = fmaxf(m0, SCALE2 * rmax0);
            float mn1 = fmaxf(m1, SCALE2 * rmax1);
            float al0 = exp2f(m0 - mn0);
            float al1 = exp2f(m1 - mn1);

            uint32_t pa[4][4];
            float rs0 = 0.0f, rs1 = 0.0f;
#pragma unroll
            for (int j = 0; j < 8; ++j) {
                float p0 = exp2f(fmaf(SCALE2, sa[j][0], -mn0));
                float p1 = exp2f(fmaf(SCALE2, sa[j][1], -mn0));
                float p2 = exp2f(fmaf(SCALE2, sa[j][2], -mn1));
                float p3 = exp2f(fmaf(SCALE2, sa[j][3], -mn1));
                rs0 += p0 + p1;
                rs1 += p2 + p3;
                pa[j >> 1][(j & 1) ? 2 : 0] = u32of(__floats2half2_rn(p0, p1));
                pa[j >> 1][(j & 1) ? 3 : 1] = u32of(__floats2half2_rn(p2, p3));
            }
#pragma unroll
            for (int off = 1; off < 4; off <<= 1) {
                rs0 += __shfl_xor_sync(0xffffffffu, rs0, off);
                rs1 += __shfl_xor_sync(0xffffffffu, rs1, off);
            }
            l0 = l0 * al0 + rs0;
            l1 = l1 * al1 + rs1;
            m0 = mn0;
            m1 = mn1;
#pragma unroll
            for (int j = 0; j < 8; ++j) {
                oac[j][0] *= al0;
                oac[j][1] *= al0;
                oac[j][2] *= al1;
                oac[j][3] *= al1;
            }

#pragma unroll
            for (int ks = 0; ks < 4; ++ks) {
                uint32_t vh[4][4];
                int row = 16 * ks + (lane & 7) + ((lane >> 3) & 1) * 8;
#pragma unroll
                for (int jp = 0; jp < 4; ++jp) {
                    int col = 16 * jp + ((lane >> 4) << 3);
                    ldsm4t(vh[jp], aV + (uint32_t)((row * AST + col) * 2));
                }
#pragma unroll
                for (int jp = 0; jp < 4; ++jp) {
                    mma_f16(oac[2 * jp],     pa[ks], vh[jp][0], vh[jp][1]);
                    mma_f16(oac[2 * jp + 1], pa[ks], vh[jp][2], vh[jp][3]);
                }
            }
            if (++stg == 3) stg = 0;
        }

        float inv0 = 1.0f / l0;
        float inv1 = 1.0f / l1;
        int row = qt * 128 + 16 * w + (lane >> 2);
        size_t ob = (size_t)row * DMODEL + h * DHEAD;
#pragma unroll
        for (int j = 0; j < 8; ++j) {
            int col = 8 * j + 2 * (lane & 3);
            *reinterpret_cast<uint32_t*>(g_ah + ob + col) =
                u32of(__floats2half2_rn(oac[j][0] * inv0, oac[j][1] * inv0));
            *reinterpret_cast<uint32_t*>(g_ah + ob + (size_t)8 * DMODEL + col) =
                u32of(__floats2half2_rn(oac[j][2] * inv1, oac[j][3] * inv1));
        }
    }
}

// ---------------------------------------------------------------------------
extern "C" void kernel_launch(void* const* d_in, const int* in_sizes, int n_in,
                              void* d_out, int out_size) {
    const float* x  = (const float*)d_in[0];
    const float* Wq = (const float*)d_in[1];
    const float* Wk = (const float*)d_in[2];
    const float* Wv = (const float*)d_in[3];
    const float* Wo = (const float*)d_in[4];
    const float* rc = (const float*)d_in[5];
    const float* rs = (const float*)d_in[6];
    float* out = (float*)d_out;

    static bool attrs_set = false;
    if (!attrs_set) {
        cudaFuncSetAttribute(attn_hmma, cudaFuncAttributeMaxDynamicSharedMemorySize,
                             ATTN_SMEM_BYTES);
        cudaFuncSetAttribute(qkv_hmma, cudaFuncAttributeMaxDynamicSharedMemorySize,
                             QKV_SMEM_BYTES);
        cudaFuncSetAttribute(out_hmma, cudaFuncAttributeMaxDynamicSharedMemorySize,
                             OUT_SMEM_BYTES);
        attrs_set = true;
    }

    // 0) One fused conversion kernel (x, Wq, Wk, Wv, Wo -> fp16)
    cvt_all_kernel<<<(2 * N4X + 2 * N4K + N4X) / 256, 256>>>(x, Wq, Wk, Wv, Wo);

    // 1) Fused QKV projection + RoPE epilogue (128x128, 3-stage)
    qkv_hmma<<<dim3(24, 16), 256, QKV_SMEM_BYTES>>>(rc, rs);

    // 2) Causal GQA attention (BQ=128, 3-stage KV prefetch, base-2 softmax)
    attn_hmma<<<dim3(8, HQ), 256, ATTN_SMEM_BYTES>>>();

    // 3) Output projection (128x256, 3-stage, hoisted fragments)
    out_hmma<<<dim3(8, 16), 256, OUT_SMEM_BYTES>>>(out);
}